// round 2
// baseline (speedup 1.0000x reference)
#include <cuda_runtime.h>
#include <cstdint>

// FactorizedSpectralConv on GB300.
// B=16, C=64, H=W=128, M0=M1=16. Only 32 kx rows (0..15, 112..127) and
// 16 ky cols of the spectrum matter -> direct small DFTs, no full FFT.
//
// K1 (per (b,t) image): F[h,ky] = sum_w X[h,w] e^{-2pi i ky w/128}  (SMEM)
//                       Xf[kx,ky] = sum_h F[h,ky] e^{-2pi i kx h/128}
//                       scaled by 1/16384 (norm="forward")
// K2 (per mode m):      Y[c,b] = sum_t W[c,t,m] * Xf[t,b,m]   (complex GEMM)
// K3 (per (b,c) image): Z[h,ky] = sum_kx Y[kx,ky] e^{+2pi i kx h/128}  (SMEM)
//                       out[h,w] = Re(Z[h,0]) + 2*sum_{ky=1..15} Re(Z[h,ky] e^{+2pi i ky w/128})

#define PI2_OVER_128 0.04908738521234051935f  // 2*pi/128

// Scratch (device globals; allocation-free rule)
__device__ float2 g_Xf[512 * 64 * 16];  // [mode][t][b], 4 MB
__device__ float2 g_Y [16 * 64 * 512];  // [b][c][mode], 4 MB

// ---------------------------------------------------------------------------
// K1: forward. grid = B*C = 1024 blocks, 128 threads (thread = h row).
// ---------------------------------------------------------------------------
__global__ void __launch_bounds__(128) k_forward(const float* __restrict__ X) {
    __shared__ float4 TWf4[128][8];   // [w][ky-pair] = (cos0,-sin0,cos1,-sin1)
    __shared__ float2 rootF[128];     // e^{-2pi i n/128}
    __shared__ float  Xs[128][17];    // 16-wide w chunk, padded
    __shared__ float2 Fw[16][129];    // [ky][h], padded

    int tid = threadIdx.x;

    // Build twiddle tables
    #pragma unroll
    for (int e = tid; e < 1024; e += 128) {
        int w = e >> 3, k2 = e & 7;
        int n0 = (w * (2 * k2)) & 127;
        int n1 = (w * (2 * k2 + 1)) & 127;
        float s0, c0, s1, c1;
        sincosf(PI2_OVER_128 * (float)n0, &s0, &c0);
        sincosf(PI2_OVER_128 * (float)n1, &s1, &c1);
        TWf4[w][k2] = make_float4(c0, -s0, c1, -s1);
    }
    {
        float s, c;
        sincosf(PI2_OVER_128 * (float)tid, &s, &c);
        rootF[tid] = make_float2(c, -s);
    }

    const float* Xp = X + (size_t)blockIdx.x * 16384;

    // Phase A: row DFT along w for this thread's row h = tid
    float ar[16], ai[16];
    #pragma unroll
    for (int k = 0; k < 16; k++) { ar[k] = 0.f; ai[k] = 0.f; }

    for (int c0 = 0; c0 < 128; c0 += 16) {
        __syncthreads();
        #pragma unroll
        for (int p = 0; p < 16; p++) {
            int i = tid + p * 128;
            int r = i >> 4, w = i & 15;
            Xs[r][w] = Xp[r * 128 + c0 + w];
        }
        __syncthreads();
        #pragma unroll
        for (int w2 = 0; w2 < 16; w2++) {
            float xv = Xs[tid][w2];
            #pragma unroll
            for (int k2 = 0; k2 < 8; k2++) {
                float4 tv = TWf4[c0 + w2][k2];
                ar[2 * k2]     += xv * tv.x;
                ai[2 * k2]     += xv * tv.y;
                ar[2 * k2 + 1] += xv * tv.z;
                ai[2 * k2 + 1] += xv * tv.w;
            }
        }
    }

    // Stash scaled row spectrum into SMEM (norm="forward": 1/(H*W))
    #pragma unroll
    for (int k = 0; k < 16; k++)
        Fw[k][tid] = make_float2(ar[k] * (1.f / 16384.f), ai[k] * (1.f / 16384.f));
    __syncthreads();

    // Phase B: column DFT along h for 32 kept kx. thread -> (ky, 4 kx)
    int ky = tid & 15, kxg = tid >> 4;
    float br[4], bi[4];
    int kxv[4], idx[4];
    #pragma unroll
    for (int j = 0; j < 4; j++) {
        br[j] = bi[j] = 0.f;
        int kxIdx = kxg * 4 + j;
        kxv[j] = (kxIdx < 16) ? kxIdx : (96 + kxIdx);  // 112..127 for bottom block
        idx[j] = 0;
    }
    for (int h = 0; h < 128; h++) {
        float2 f = Fw[ky][h];
        #pragma unroll
        for (int j = 0; j < 4; j++) {
            float2 e = rootF[idx[j]];
            br[j] += f.x * e.x - f.y * e.y;
            bi[j] += f.x * e.y + f.y * e.x;
            idx[j] = (idx[j] + kxv[j]) & 127;
        }
    }

    int b = blockIdx.x >> 6, t = blockIdx.x & 63;
    #pragma unroll
    for (int j = 0; j < 4; j++) {
        int m = (kxg * 4 + j) * 16 + ky;
        g_Xf[(m * 64 + t) * 16 + b] = make_float2(br[j], bi[j]);
    }
}

// ---------------------------------------------------------------------------
// K2: mode mixing. grid = 512 modes, 256 threads. thread -> (4 c, 1 b).
// ---------------------------------------------------------------------------
__global__ void __launch_bounds__(256) k_modes(
    const float* __restrict__ w0r, const float* __restrict__ w0i,
    const float* __restrict__ w1r, const float* __restrict__ w1i) {
    __shared__ float2 Ws[64][65];   // [c][t], padded
    __shared__ float2 Xs[64][17];   // [t][b], padded

    int m = blockIdx.x;
    int kxIdx = m >> 4, ky = m & 15;
    const float* Wr = (kxIdx < 16) ? w0r : w1r;
    const float* Wi = (kxIdx < 16) ? w0i : w1i;
    int kx0 = (kxIdx < 16) ? kxIdx : (kxIdx - 16);
    int woff = kx0 * 16 + ky;
    int tid = threadIdx.x;

    #pragma unroll
    for (int p = 0; p < 16; p++) {
        int i = tid + p * 256;                       // i = c*64 + t
        Ws[i >> 6][i & 63] = make_float2(Wr[i * 256 + woff], Wi[i * 256 + woff]);
    }
    #pragma unroll
    for (int p = 0; p < 4; p++) {
        int i = tid + p * 256;                       // i = t*16 + b
        Xs[i >> 4][i & 15] = g_Xf[m * 1024 + i];
    }
    __syncthreads();

    int b = tid & 15, cq = tid >> 4;
    float yr[4] = {0.f, 0.f, 0.f, 0.f}, yi[4] = {0.f, 0.f, 0.f, 0.f};
    for (int t = 0; t < 64; t++) {
        float2 xv = Xs[t][b];
        #pragma unroll
        for (int j = 0; j < 4; j++) {
            float2 w = Ws[cq * 4 + j][t];
            yr[j] += w.x * xv.x - w.y * xv.y;
            yi[j] += w.x * xv.y + w.y * xv.x;
        }
    }
    #pragma unroll
    for (int j = 0; j < 4; j++) {
        int c = cq * 4 + j;
        g_Y[(size_t)(b * 64 + c) * 512 + m] = make_float2(yr[j], yi[j]);
    }
}

// ---------------------------------------------------------------------------
// K3: inverse. grid = B*C = 1024 blocks, 256 threads.
// ---------------------------------------------------------------------------
__global__ void __launch_bounds__(256) k_inverse(float* __restrict__ out) {
    __shared__ float2 rootI[128];     // e^{+2pi i n/128}
    __shared__ float2 Ys[32][16];     // [kxIdx][ky]
    __shared__ float4 Zs4[128][9];    // [h][ky-pair], row pitch 9 (8 used)

    int tid = threadIdx.x;
    if (tid < 128) {
        float s, c;
        sincosf(PI2_OVER_128 * (float)tid, &s, &c);
        rootI[tid] = make_float2(c, s);
    }
    const float2* Yp = g_Y + (size_t)blockIdx.x * 512;
    #pragma unroll
    for (int p = 0; p < 2; p++) {
        int i = tid + p * 256;
        ((float2*)Ys)[i] = Yp[i];
    }
    __syncthreads();

    // Phase A: Z[h,ky] = sum_kx Y[kx,ky] e^{+2pi i kx h/128}
    {
        int ky = tid & 15, hg = tid >> 4;   // thread handles h = hg + 16*j
        float zr[8], zi[8];
        int idx[8];
        #pragma unroll
        for (int j = 0; j < 8; j++) { zr[j] = 0.f; zi[j] = 0.f; idx[j] = 0; }

        // kx = 0..15
        for (int kxIdx = 0; kxIdx < 16; kxIdx++) {
            float2 y = Ys[kxIdx][ky];
            #pragma unroll
            for (int j = 0; j < 8; j++) {
                int h = hg + 16 * j;
                float2 e = rootI[idx[j]];
                zr[j] += y.x * e.x - y.y * e.y;
                zi[j] += y.x * e.y + y.y * e.x;
                idx[j] = (idx[j] + h) & 127;
            }
        }
        // kx = 112..127
        #pragma unroll
        for (int j = 0; j < 8; j++) idx[j] = (112 * (hg + 16 * j)) & 127;
        for (int kxIdx = 16; kxIdx < 32; kxIdx++) {
            float2 y = Ys[kxIdx][ky];
            #pragma unroll
            for (int j = 0; j < 8; j++) {
                int h = hg + 16 * j;
                float2 e = rootI[idx[j]];
                zr[j] += y.x * e.x - y.y * e.y;
                zi[j] += y.x * e.y + y.y * e.x;
                idx[j] = (idx[j] + h) & 127;
            }
        }
        #pragma unroll
        for (int j = 0; j < 8; j++) {
            int h = hg + 16 * j;
            ((float2*)&Zs4[h][0])[ky] = make_float2(zr[j], zi[j]);
        }
    }
    __syncthreads();

    // Phase B: thread -> (w, row-group). Twiddles live in registers;
    // Zs reads are warp-broadcast; output stores are coalesced along w.
    int w = tid & 127, rg = tid >> 7;
    float tc[16], ts[16];
    tc[0] = 1.f; ts[0] = 0.f;                 // DC: Re(Z0), not doubled
    #pragma unroll
    for (int k = 1; k < 16; k++) {
        float2 e = rootI[(k * w) & 127];
        tc[k] = 2.f * e.x;
        ts[k] = 2.f * e.y;
    }
    float* op = out + (size_t)blockIdx.x * 16384;
    for (int i = 0; i < 64; i++) {
        int r = rg * 64 + i;
        float acc = 0.f;
        #pragma unroll
        for (int k2 = 0; k2 < 8; k2++) {
            float4 z = Zs4[r][k2];   // (zr0, zi0, zr1, zi1)
            acc += z.x * tc[2 * k2]     - z.y * ts[2 * k2];
            acc += z.z * tc[2 * k2 + 1] - z.w * ts[2 * k2 + 1];
        }
        op[r * 128 + w] = acc;
    }
}

// ---------------------------------------------------------------------------
extern "C" void kernel_launch(void* const* d_in, const int* in_sizes, int n_in,
                              void* d_out, int out_size) {
    const float* X   = (const float*)d_in[0];
    const float* w0r = (const float*)d_in[1];
    const float* w0i = (const float*)d_in[2];
    const float* w1r = (const float*)d_in[3];
    const float* w1i = (const float*)d_in[4];
    float* out = (float*)d_out;

    k_forward<<<1024, 128>>>(X);
    k_modes<<<512, 256>>>(w0r, w0i, w1r, w1i);
    k_inverse<<<1024, 256>>>(out);
}

// round 4
// speedup vs baseline: 1.2449x; 1.2449x over previous
#include <cuda_runtime.h>
#include <cstdint>

// FactorizedSpectralConv on GB300 — f32x2-packed direct DFTs, no full FFT.
// B=16, C=64, H=W=128, M0=M1=16.

typedef unsigned long long ull;
#define PI2_OVER_128 0.04908738521234051935f  // 2*pi/128

// Scratch (device globals; allocation-free rule)
__device__ float2 g_Xf[512 * 1024];   // [m][t*16+b], 4 MB
__device__ float2 g_Y [512 * 1024];   // [m][b*64+c], 4 MB
__device__ float2 g_W [512 * 4096];   // [m][c*64+t], 16 MB (transposed weights)

__device__ __forceinline__ ull pk2(float x, float y) {
    ull r; asm("mov.b64 %0,{%1,%2};" : "=l"(r) : "f"(x), "f"(y)); return r;
}
__device__ __forceinline__ void upk2(ull v, float& x, float& y) {
    asm("mov.b64 {%0,%1},%2;" : "=f"(x), "=f"(y) : "l"(v));
}
__device__ __forceinline__ void fma2(ull& d, ull a, ull b) {
    asm("fma.rn.f32x2 %0,%1,%2,%0;" : "+l"(d) : "l"(a), "l"(b));
}
__device__ __forceinline__ ull add2(ull a, ull b) {
    ull d; asm("add.rn.f32x2 %0,%1,%2;" : "=l"(d) : "l"(a), "l"(b)); return d;
}

// ---------------------------------------------------------------------------
// K0: weight transpose  w[c][t][kx0][ky] (stride-256 cols) -> g_W[m][c*64+t]
// grid = 2048 (2 arrays x 128 ct-tiles x 8 m-tiles), 256 threads
// ---------------------------------------------------------------------------
__global__ void __launch_bounds__(256) k_transpose(
    const float* __restrict__ w0r, const float* __restrict__ w0i,
    const float* __restrict__ w1r, const float* __restrict__ w1i) {
    __shared__ float Tr[32][33], Ti[32][33];
    int bid = blockIdx.x;
    int arr = bid >> 10;
    int tix = bid & 1023;
    int ctTile = tix >> 3, mTile = tix & 7;
    const float* Sr = arr ? w1r : w0r;
    const float* Si = arr ? w1i : w0i;
    int tx = threadIdx.x & 31, ty = threadIdx.x >> 5;
    #pragma unroll
    for (int yy = 0; yy < 4; yy++) {
        int r = ty + yy * 8;
        int row = ctTile * 32 + r, col = mTile * 32 + tx;
        Tr[r][tx] = Sr[row * 256 + col];
        Ti[r][tx] = Si[row * 256 + col];
    }
    __syncthreads();
    #pragma unroll
    for (int yy = 0; yy < 4; yy++) {
        int r = ty + yy * 8;
        int m = arr * 256 + mTile * 32 + r;
        int ct = ctTile * 32 + tx;
        g_W[(size_t)m * 4096 + ct] = make_float2(Tr[tx][r], Ti[tx][r]);
    }
}

// ---------------------------------------------------------------------------
// K1: forward. grid = B*C = 1024 blocks, 128 threads (thread = h row).
// ---------------------------------------------------------------------------
__global__ void __launch_bounds__(128) k_forward(const float* __restrict__ X) {
    __shared__ __align__(16) ull TWA[128][16];  // (cos,-sin)/16384, 16KB
    __shared__ __align__(16) ull TWB[128][2];   // (c,-s),(s,c), 2KB
    __shared__ float  Xs[128][17];              // 8.5KB
    __shared__ float2 Fw[16][129];              // row spectrum, 16.5KB

    int tid = threadIdx.x;

    #pragma unroll
    for (int e = tid; e < 2048; e += 128) {
        int w = e >> 4, k = e & 15;
        float s, c; sincosf(PI2_OVER_128 * (float)((w * k) & 127), &s, &c);
        TWA[w][k] = pk2(c * (1.f / 16384.f), -s * (1.f / 16384.f));
    }
    {
        float s, c; sincosf(PI2_OVER_128 * (float)tid, &s, &c);
        TWB[tid][0] = pk2(c, -s);
        TWB[tid][1] = pk2(s, c);
    }

    const float* Xp = X + (size_t)blockIdx.x * 16384;

    // Phase A: F[h,ky] = sum_w X[h,w] e^{-2pi i ky w/128}, packed (re,im)
    ull acc[16];
    #pragma unroll
    for (int k = 0; k < 16; k++) acc[k] = 0;

    for (int c0 = 0; c0 < 128; c0 += 16) {
        __syncthreads();
        #pragma unroll
        for (int p = 0; p < 4; p++) {
            int i = tid + p * 128;
            int r = i >> 2, q = i & 3;
            float4 v = *(const float4*)(Xp + r * 128 + c0 + q * 4);
            Xs[r][q * 4 + 0] = v.x; Xs[r][q * 4 + 1] = v.y;
            Xs[r][q * 4 + 2] = v.z; Xs[r][q * 4 + 3] = v.w;
        }
        __syncthreads();
        #pragma unroll
        for (int w2 = 0; w2 < 16; w2++) {
            float xv = Xs[tid][w2];
            ull xp = pk2(xv, xv);
            const ulonglong2* tw = (const ulonglong2*)&TWA[c0 + w2][0];
            #pragma unroll
            for (int k4 = 0; k4 < 8; k4++) {
                ulonglong2 tp = tw[k4];
                fma2(acc[2 * k4],     xp, tp.x);
                fma2(acc[2 * k4 + 1], xp, tp.y);
            }
        }
    }

    #pragma unroll
    for (int k = 0; k < 16; k++) {
        float re, im; upk2(acc[k], re, im);
        Fw[k][tid] = make_float2(re, im);
    }
    __syncthreads();

    // Phase B: Xf[kx,ky] = sum_h F[h,ky] e^{-2pi i kx h/128}
    int ky = tid & 15, kxg = tid >> 4;
    ull accB[4] = {0, 0, 0, 0}, accC[4] = {0, 0, 0, 0};
    int kxv[4], idx[4];
    #pragma unroll
    for (int j = 0; j < 4; j++) {
        int kxIdx = kxg * 4 + j;
        kxv[j] = (kxIdx < 16) ? kxIdx : (96 + kxIdx);  // 112..127 for bottom
        idx[j] = 0;
    }
    for (int h = 0; h < 128; h++) {
        float2 f = Fw[ky][h];
        ull fR = pk2(f.x, f.x), fI = pk2(f.y, f.y);
        #pragma unroll
        for (int j = 0; j < 4; j++) {
            ulonglong2 e = *(const ulonglong2*)&TWB[idx[j]][0];
            fma2(accB[j], fR, e.x);
            fma2(accC[j], fI, e.y);
            idx[j] = (idx[j] + kxv[j]) & 127;
        }
    }
    int b = blockIdx.x >> 6, t = blockIdx.x & 63;
    #pragma unroll
    for (int j = 0; j < 4; j++) {
        int m = (kxg * 4 + j) * 16 + ky;
        ull r = add2(accB[j], accC[j]);
        float re, im; upk2(r, re, im);
        g_Xf[m * 1024 + t * 16 + b] = make_float2(re, im);
    }
}

// ---------------------------------------------------------------------------
// K2: mode mixing. grid = 512 modes, 256 threads, dynamic SMEM 91136B.
// ---------------------------------------------------------------------------
__global__ void __launch_bounds__(256) k_modes() {
    extern __shared__ __align__(16) char sm2[];
    ulonglong2* Wsp = (ulonglong2*)sm2;                        // [64 t][65] pitch
    ulonglong2* Xsm = (ulonglong2*)(sm2 + 64 * 65 * 16);       // [64 t][16 b]
    ull*        Ys2 = (ull*)(sm2 + 64 * 65 * 16 + 64 * 16 * 16); // [1024]

    int m = blockIdx.x, tid = threadIdx.x;

    #pragma unroll
    for (int p = 0; p < 16; p++) {
        int i = tid + p * 256;                 // i = c*64 + t
        float2 w = g_W[(size_t)m * 4096 + i];
        Wsp[(i & 63) * 65 + (i >> 6)] = make_ulonglong2(pk2(w.x, w.x), pk2(w.y, w.y));
    }
    #pragma unroll
    for (int p = 0; p < 4; p++) {
        int i = tid + p * 256;                 // i = t*16 + b
        float2 x = g_Xf[m * 1024 + i];
        Xsm[i] = make_ulonglong2(pk2(x.x, x.y), pk2(-x.y, x.x));
    }
    __syncthreads();

    int b = tid >> 4, cf = tid & 15;
    ull acc[4] = {0, 0, 0, 0};
    for (int t = 0; t < 64; t++) {
        ulonglong2 xv = Xsm[t * 16 + b];
        #pragma unroll
        for (int j = 0; j < 4; j++) {
            ulonglong2 wv = Wsp[t * 65 + j * 16 + cf];
            fma2(acc[j], wv.x, xv.x);   // (yr,yi) += (wr,wr)*(xr,xi)
            fma2(acc[j], wv.y, xv.y);   //          + (wi,wi)*(-xi,xr)
        }
    }
    #pragma unroll
    for (int j = 0; j < 4; j++) Ys2[b * 64 + j * 16 + cf] = acc[j];
    __syncthreads();
    #pragma unroll
    for (int p = 0; p < 4; p++) {              // FIX: was p < 2 (dropped b>=8)
        int i = tid + p * 256;
        *(ull*)&g_Y[(size_t)m * 1024 + i] = Ys2[i];
    }
}

// ---------------------------------------------------------------------------
// K3: inverse. grid = B*C = 1024 blocks, 256 threads.
// ---------------------------------------------------------------------------
__global__ void __launch_bounds__(256) k_inverse(float* __restrict__ out) {
    __shared__ __align__(16) ull TWI[128][2];   // (c,s),(-s,c)
    __shared__ ull Ysm[512];
    __shared__ __align__(16) ull ZR[64][18];    // packed (zr_h, zr_{h+64})
    __shared__ __align__(16) ull ZI[64][18];

    int tid = threadIdx.x;
    if (tid < 128) {
        float s, c; sincosf(PI2_OVER_128 * (float)tid, &s, &c);
        TWI[tid][0] = pk2(c, s);
        TWI[tid][1] = pk2(-s, c);
    }
    int off = blockIdx.x;   // b*64 + c
    Ysm[tid]       = *(const ull*)&g_Y[(size_t)tid * 1024 + off];
    Ysm[tid + 256] = *(const ull*)&g_Y[(size_t)(tid + 256) * 1024 + off];
    __syncthreads();

    // Phase A: Z[h,ky] = sum_kx Y[kx,ky] e^{+2pi i kx h/128}
    // twiddle(kx, h+64) = (-1)^kx twiddle(kx, h): one LDS serves two rows.
    {
        int ky = tid & 15, hg = tid >> 4;
        ull accZ[8] = {0, 0, 0, 0, 0, 0, 0, 0};
        int idx[4];
        #pragma unroll
        for (int j = 0; j < 4; j++) idx[j] = 0;

        for (int kxI = 0; kxI < 16; kxI++) {            // kx = kxI
            float yr, yi; upk2(Ysm[kxI * 16 + ky], yr, yi);
            float syr = (kxI & 1) ? -yr : yr;
            float syi = (kxI & 1) ? -yi : yi;
            ull pr = pk2(yr, yr),  pi = pk2(yi, yi);
            ull qr = pk2(syr, syr), qi = pk2(syi, syi);
            #pragma unroll
            for (int j = 0; j < 4; j++) {
                ulonglong2 e = *(const ulonglong2*)&TWI[idx[j]][0];
                fma2(accZ[j],     pr, e.x); fma2(accZ[j],     pi, e.y);
                fma2(accZ[j + 4], qr, e.x); fma2(accZ[j + 4], qi, e.y);
                idx[j] = (idx[j] + hg + 16 * j) & 127;
            }
        }
        #pragma unroll
        for (int j = 0; j < 4; j++) idx[j] = (112 * (hg + 16 * j)) & 127;
        for (int kxI = 16; kxI < 32; kxI++) {           // kx = 96 + kxI
            float yr, yi; upk2(Ysm[kxI * 16 + ky], yr, yi);
            float syr = (kxI & 1) ? -yr : yr;           // kx parity == kxI parity
            float syi = (kxI & 1) ? -yi : yi;
            ull pr = pk2(yr, yr),  pi = pk2(yi, yi);
            ull qr = pk2(syr, syr), qi = pk2(syi, syi);
            #pragma unroll
            for (int j = 0; j < 4; j++) {
                ulonglong2 e = *(const ulonglong2*)&TWI[idx[j]][0];
                fma2(accZ[j],     pr, e.x); fma2(accZ[j],     pi, e.y);
                fma2(accZ[j + 4], qr, e.x); fma2(accZ[j + 4], qi, e.y);
                idx[j] = (idx[j] + hg + 16 * j) & 127;
            }
        }
        #pragma unroll
        for (int p = 0; p < 4; p++) {
            int r = hg + 16 * p;                        // h' in 0..63
            float a0, b0, a1, b1;
            upk2(accZ[p],     a0, b0);                  // h = r
            upk2(accZ[p + 4], a1, b1);                  // h = r + 64
            ZR[r][ky] = pk2(a0, a1);
            ZI[r][ky] = pk2(b0, b1);
        }
    }
    __syncthreads();

    // Phase B: out[h,w] = Re(Z[h,0]) + 2*sum_{ky=1..15} Re(Z[h,ky] e^{+2pi i ky w/128})
    int w = tid & 127, rg = tid >> 7;
    ull tc[16], ts[16];
    tc[0] = pk2(1.f, 1.f); ts[0] = 0;
    #pragma unroll
    for (int k = 1; k < 16; k++) {
        float c, s; upk2(TWI[(k * w) & 127][0], c, s);
        tc[k] = pk2(2.f * c, 2.f * c);
        ts[k] = pk2(-2.f * s, -2.f * s);
    }
    float* op = out + (size_t)blockIdx.x * 16384;
    for (int i = 0; i < 32; i++) {
        int r = rg * 32 + i;
        ull accA = 0, accB = 0;
        const ulonglong2* zr2 = (const ulonglong2*)&ZR[r][0];
        const ulonglong2* zi2 = (const ulonglong2*)&ZI[r][0];
        #pragma unroll
        for (int k2 = 0; k2 < 8; k2++) {
            ulonglong2 a = zr2[k2];
            fma2(accA, a.x, tc[2 * k2]);
            fma2(accB, a.y, tc[2 * k2 + 1]);
            ulonglong2 bq = zi2[k2];
            fma2(accA, bq.x, ts[2 * k2]);
            fma2(accB, bq.y, ts[2 * k2 + 1]);
        }
        ull acc = add2(accA, accB);
        float o0, o1; upk2(acc, o0, o1);
        op[r * 128 + w] = o0;
        op[(r + 64) * 128 + w] = o1;
    }
}

// ---------------------------------------------------------------------------
extern "C" void kernel_launch(void* const* d_in, const int* in_sizes, int n_in,
                              void* d_out, int out_size) {
    const float* X   = (const float*)d_in[0];
    const float* w0r = (const float*)d_in[1];
    const float* w0i = (const float*)d_in[2];
    const float* w1r = (const float*)d_in[3];
    const float* w1i = (const float*)d_in[4];
    float* out = (float*)d_out;

    static bool attr_done = false;
    if (!attr_done) {
        cudaFuncSetAttribute(k_modes, cudaFuncAttributeMaxDynamicSharedMemorySize,
                             91136);
        attr_done = true;
    }

    k_transpose<<<2048, 256>>>(w0r, w0i, w1r, w1i);
    k_forward<<<1024, 128>>>(X);
    k_modes<<<512, 256, 91136>>>();
    k_inverse<<<1024, 256>>>(out);
}

// round 5
// speedup vs baseline: 1.5730x; 1.2635x over previous
#include <cuda_runtime.h>
#include <cstdint>

// FactorizedSpectralConv on GB300 — f32x2-packed radix-2 folded DFTs.
// B=16, C=64, H=W=128, M0=M1=16.

typedef unsigned long long ull;
#define PI2_OVER_128 0.04908738521234051935f  // 2*pi/128
#define SGN2 0x8000000080000000ULL

// Scratch (device globals; allocation-free rule)
__device__ float2 g_Xf[512 * 1024];   // [m][t*16+b], 4 MB
__device__ float2 g_Y [512 * 1024];   // [m][b*64+c], 4 MB
__device__ float2 g_W [512 * 4096];   // [m][c*64+t], 16 MB (transposed weights)

__device__ __forceinline__ ull pk2(float x, float y) {
    ull r; asm("mov.b64 %0,{%1,%2};" : "=l"(r) : "f"(x), "f"(y)); return r;
}
__device__ __forceinline__ void upk2(ull v, float& x, float& y) {
    asm("mov.b64 {%0,%1},%2;" : "=f"(x), "=f"(y) : "l"(v));
}
__device__ __forceinline__ void fma2(ull& d, ull a, ull b) {
    asm("fma.rn.f32x2 %0,%1,%2,%0;" : "+l"(d) : "l"(a), "l"(b));
}
__device__ __forceinline__ ull add2(ull a, ull b) {
    ull d; asm("add.rn.f32x2 %0,%1,%2;" : "=l"(d) : "l"(a), "l"(b)); return d;
}
__device__ __forceinline__ ull sub2(ull a, ull b) {   // a - b via sign-flip + add
    return add2(a, b ^ SGN2);
}

// ---------------------------------------------------------------------------
// K0: weight transpose  w[c][t][kx0][ky] (stride-256 cols) -> g_W[m][c*64+t]
// ---------------------------------------------------------------------------
__global__ void __launch_bounds__(256) k_transpose(
    const float* __restrict__ w0r, const float* __restrict__ w0i,
    const float* __restrict__ w1r, const float* __restrict__ w1i) {
    __shared__ float Tr[32][33], Ti[32][33];
    int bid = blockIdx.x;
    int arr = bid >> 10;
    int tix = bid & 1023;
    int ctTile = tix >> 3, mTile = tix & 7;
    const float* Sr = arr ? w1r : w0r;
    const float* Si = arr ? w1i : w0i;
    int tx = threadIdx.x & 31, ty = threadIdx.x >> 5;
    #pragma unroll
    for (int yy = 0; yy < 4; yy++) {
        int r = ty + yy * 8;
        int row = ctTile * 32 + r, col = mTile * 32 + tx;
        Tr[r][tx] = Sr[row * 256 + col];
        Ti[r][tx] = Si[row * 256 + col];
    }
    __syncthreads();
    #pragma unroll
    for (int yy = 0; yy < 4; yy++) {
        int r = ty + yy * 8;
        int m = arr * 256 + mTile * 32 + r;
        int ct = ctTile * 32 + tx;
        g_W[(size_t)m * 4096 + ct] = make_float2(Tr[tx][r], Ti[tx][r]);
    }
}

// ---------------------------------------------------------------------------
// K1: forward. grid = B*C = 1024 blocks, 128 threads (thread = h row).
// Radix-2 fold in w (phase A) and h (phase B).
// ---------------------------------------------------------------------------
__global__ void __launch_bounds__(128) k_forward(const float* __restrict__ X) {
    __shared__ __align__(16) ull TWA[64][16];   // (c,-s)/16384, w<64 — 8KB
    __shared__ __align__(16) ull TWB[128][2];   // (c,-s),(s,c) — 2KB
    __shared__ float Xs[128][33];               // lo 0..15, hi 16..31 — 16.9KB
    __shared__ ull   Fw[16][129];               // packed F[ky][h], odd pitch — 16.5KB

    int tid = threadIdx.x;

    #pragma unroll
    for (int e = tid; e < 1024; e += 128) {
        int w = e >> 4, k = e & 15;
        float s, c; sincosf(PI2_OVER_128 * (float)((w * k) & 127), &s, &c);
        TWA[w][k] = pk2(c * (1.f / 16384.f), -s * (1.f / 16384.f));
    }
    {
        float s, c; sincosf(PI2_OVER_128 * (float)tid, &s, &c);
        TWB[tid][0] = pk2(c, -s);
        TWB[tid][1] = pk2(s, c);
    }

    const float* Xp = X + (size_t)blockIdx.x * 16384;

    // Phase A: F[h,ky] = sum_{w<64} (X[w] +/- X[w+64]) e^{-2pi i ky w/128}
    ull acc[16];
    #pragma unroll
    for (int k = 0; k < 16; k++) acc[k] = 0;

    for (int c0 = 0; c0 < 64; c0 += 16) {
        __syncthreads();
        #pragma unroll
        for (int p = 0; p < 8; p++) {
            int i = p * 128 + tid;
            int r = i >> 3, q = i & 7;
            const float* src = (q < 4) ? (Xp + r * 128 + c0 + q * 4)
                                       : (Xp + r * 128 + c0 + 64 + (q - 4) * 4);
            float4 v = *(const float4*)src;
            int col = (q < 4) ? q * 4 : 16 + (q - 4) * 4;
            Xs[r][col + 0] = v.x; Xs[r][col + 1] = v.y;
            Xs[r][col + 2] = v.z; Xs[r][col + 3] = v.w;
        }
        __syncthreads();
        #pragma unroll
        for (int w2 = 0; w2 < 16; w2++) {
            float xlo = Xs[tid][w2], xhi = Xs[tid][16 + w2];
            float xp = xlo + xhi, xm = xlo - xhi;
            ull xpp = pk2(xp, xp), xmp = pk2(xm, xm);
            const ulonglong2* tw = (const ulonglong2*)&TWA[c0 + w2][0];
            #pragma unroll
            for (int k4 = 0; k4 < 8; k4++) {
                ulonglong2 tp = tw[k4];
                fma2(acc[2 * k4],     xpp, tp.x);   // even ky <- x+ fold
                fma2(acc[2 * k4 + 1], xmp, tp.y);   // odd  ky <- x- fold
            }
        }
    }

    #pragma unroll
    for (int k = 0; k < 16; k++) Fw[k][tid] = acc[k];
    __syncthreads();

    // Phase B: Xf[kx,ky] = sum_{h<64} (F[h] +/- F[h+64]) e^{-2pi i kx h/128}
    int ky = tid & 15, kxg = tid >> 4;
    ull accB[4] = {0, 0, 0, 0}, accC[4] = {0, 0, 0, 0};
    int kxv[4], idx[4];
    #pragma unroll
    for (int j = 0; j < 4; j++) {
        int kxIdx = kxg * 4 + j;
        kxv[j] = (kxIdx < 16) ? kxIdx : (96 + kxIdx);  // parity(kxv) == parity(j)
        idx[j] = 0;
    }
    for (int h = 0; h < 64; h++) {
        ull a = Fw[ky][h], b = Fw[ky][h + 64];
        ull p = add2(a, b), m = sub2(a, b);
        float pr, pi, mr, mi;
        upk2(p, pr, pi); upk2(m, mr, mi);
        ull prr = pk2(pr, pr), pii = pk2(pi, pi);
        ull mrr = pk2(mr, mr), mii = pk2(mi, mi);
        #pragma unroll
        for (int j = 0; j < 4; j++) {
            ulonglong2 e = *(const ulonglong2*)&TWB[idx[j]][0];
            if (j & 1) { fma2(accB[j], mrr, e.x); fma2(accC[j], mii, e.y); }
            else       { fma2(accB[j], prr, e.x); fma2(accC[j], pii, e.y); }
            idx[j] = (idx[j] + kxv[j]) & 127;
        }
    }
    int b = blockIdx.x >> 6, t = blockIdx.x & 63;
    #pragma unroll
    for (int j = 0; j < 4; j++) {
        int m = (kxg * 4 + j) * 16 + ky;
        ull r = add2(accB[j], accC[j]);
        float re, im; upk2(r, re, im);
        g_Xf[m * 1024 + t * 16 + b] = make_float2(re, im);
    }
}

// ---------------------------------------------------------------------------
// K2: mode mixing. grid = 512 modes, 256 threads, dynamic SMEM 91136B.
// ---------------------------------------------------------------------------
__global__ void __launch_bounds__(256) k_modes() {
    extern __shared__ __align__(16) char sm2[];
    ulonglong2* Wsp = (ulonglong2*)sm2;                          // [64 t][65]
    ulonglong2* Xsm = (ulonglong2*)(sm2 + 64 * 65 * 16);         // [64 t][16 b]
    ull*        Ys2 = (ull*)(sm2 + 64 * 65 * 16 + 64 * 16 * 16); // [1024]

    int m = blockIdx.x, tid = threadIdx.x;

    #pragma unroll
    for (int p = 0; p < 16; p++) {
        int i = tid + p * 256;                 // i = c*64 + t
        float2 w = g_W[(size_t)m * 4096 + i];
        Wsp[(i & 63) * 65 + (i >> 6)] = make_ulonglong2(pk2(w.x, w.x), pk2(w.y, w.y));
    }
    #pragma unroll
    for (int p = 0; p < 4; p++) {
        int i = tid + p * 256;                 // i = t*16 + b
        float2 x = g_Xf[m * 1024 + i];
        Xsm[i] = make_ulonglong2(pk2(x.x, x.y), pk2(-x.y, x.x));
    }
    __syncthreads();

    int b = tid >> 4, cf = tid & 15;
    ull acc[4] = {0, 0, 0, 0};
    for (int t = 0; t < 64; t++) {
        ulonglong2 xv = Xsm[t * 16 + b];
        #pragma unroll
        for (int j = 0; j < 4; j++) {
            ulonglong2 wv = Wsp[t * 65 + j * 16 + cf];
            fma2(acc[j], wv.x, xv.x);
            fma2(acc[j], wv.y, xv.y);
        }
    }
    #pragma unroll
    for (int j = 0; j < 4; j++) Ys2[b * 64 + j * 16 + cf] = acc[j];
    __syncthreads();
    #pragma unroll
    for (int p = 0; p < 4; p++) {
        int i = tid + p * 256;
        *(ull*)&g_Y[(size_t)m * 1024 + i] = Ys2[i];
    }
}

// ---------------------------------------------------------------------------
// K3: inverse. grid = B*C = 1024 blocks, 256 threads.
// Radix-2 fold in kx parity (phase A) and w (phase B).
// ---------------------------------------------------------------------------
__global__ void __launch_bounds__(256) k_inverse(float* __restrict__ out) {
    __shared__ __align__(16) ull TWI[128][2];     // (c,s),(-s,c) — 2KB
    __shared__ ull Ysm[512];                      // 4KB
    __shared__ __align__(16) ulonglong2 ZZ[64][17]; // [(zr_h,zr_h64),(zi_h,zi_h64)] — 17.4KB

    int tid = threadIdx.x;
    if (tid < 128) {
        float s, c; sincosf(PI2_OVER_128 * (float)tid, &s, &c);
        TWI[tid][0] = pk2(c, s);
        TWI[tid][1] = pk2(-s, c);
    }
    int off = blockIdx.x;   // b*64 + c
    Ysm[tid]       = *(const ull*)&g_Y[(size_t)tid * 1024 + off];
    Ysm[tid + 256] = *(const ull*)&g_Y[(size_t)(tid + 256) * 1024 + off];
    __syncthreads();

    // Phase A: Z[h] = Se+So, Z[h+64] = Se-So  (Se/So = even/odd-kx partial sums)
    {
        int ky = tid & 15, hg = tid >> 4;          // h = hg + 16j, j=0..3 (h<64)
        ull Se[4] = {0, 0, 0, 0}, So[4] = {0, 0, 0, 0};
        int hh[4], idx[4];
        #pragma unroll
        for (int j = 0; j < 4; j++) { hh[j] = hg + 16 * j; idx[j] = 0; }

        #pragma unroll
        for (int kxI = 0; kxI < 16; kxI++) {       // kx = kxI
            float yr, yi; upk2(Ysm[kxI * 16 + ky], yr, yi);
            ull yrr = pk2(yr, yr), yii = pk2(yi, yi);
            #pragma unroll
            for (int j = 0; j < 4; j++) {
                ulonglong2 e = *(const ulonglong2*)&TWI[idx[j]][0];
                if (kxI & 1) { fma2(So[j], yrr, e.x); fma2(So[j], yii, e.y); }
                else         { fma2(Se[j], yrr, e.x); fma2(Se[j], yii, e.y); }
                idx[j] = (idx[j] + hh[j]) & 127;
            }
        }
        #pragma unroll
        for (int j = 0; j < 4; j++) idx[j] = (112 * hh[j]) & 127;
        #pragma unroll
        for (int kxI = 16; kxI < 32; kxI++) {      // kx = 96 + kxI, parity(kx)=parity(kxI)
            float yr, yi; upk2(Ysm[kxI * 16 + ky], yr, yi);
            ull yrr = pk2(yr, yr), yii = pk2(yi, yi);
            #pragma unroll
            for (int j = 0; j < 4; j++) {
                ulonglong2 e = *(const ulonglong2*)&TWI[idx[j]][0];
                if (kxI & 1) { fma2(So[j], yrr, e.x); fma2(So[j], yii, e.y); }
                else         { fma2(Se[j], yrr, e.x); fma2(Se[j], yii, e.y); }
                idx[j] = (idx[j] + hh[j]) & 127;
            }
        }
        #pragma unroll
        for (int j = 0; j < 4; j++) {
            int r = hh[j];
            ull zp = add2(Se[j], So[j]);   // h = r
            ull zm = sub2(Se[j], So[j]);   // h = r + 64
            float pr, pi, mr, mi;
            upk2(zp, pr, pi); upk2(zm, mr, mi);
            ZZ[r][ky] = make_ulonglong2(pk2(pr, mr), pk2(pi, mi));
        }
    }
    __syncthreads();

    // Phase B: out[r,w]    = accE + accO  (even/odd ky partial sums)
    //          out[r,w+64] = accE - accO
    // Outer loop over ky; accumulators (16 rows x E/O) live in registers.
    int wl = tid & 63, rg = tid >> 6;      // rows r = rg*16 + i
    ull accE[16], accO[16];
    {
        // ky = 0 init: accE = zr-pair (Re(Z0) only), accO = 0
        #pragma unroll
        for (int i = 0; i < 16; i++) {
            accE[i] = ZZ[rg * 16 + i][0].x;
            accO[i] = 0;
        }
        #pragma unroll
        for (int k = 1; k < 16; k++) {
            float c, s; upk2(TWI[(k * wl) & 127][0], c, s);
            ull tcp = pk2(2.f * c, 2.f * c);
            ull tsp = pk2(-2.f * s, -2.f * s);
            if (k & 1) {
                #pragma unroll
                for (int i = 0; i < 16; i++) {
                    ulonglong2 zz = ZZ[rg * 16 + i][k];
                    fma2(accO[i], zz.x, tcp);
                    fma2(accO[i], zz.y, tsp);
                }
            } else {
                #pragma unroll
                for (int i = 0; i < 16; i++) {
                    ulonglong2 zz = ZZ[rg * 16 + i][k];
                    fma2(accE[i], zz.x, tcp);
                    fma2(accE[i], zz.y, tsp);
                }
            }
        }
    }
    float* op = out + (size_t)blockIdx.x * 16384;
    #pragma unroll
    for (int i = 0; i < 16; i++) {
        int r = rg * 16 + i;
        ull olo = add2(accE[i], accO[i]);   // w = wl
        ull ohi = sub2(accE[i], accO[i]);   // w = wl + 64
        float a0, a1, b0, b1;
        upk2(olo, a0, a1);                  // (h=r, h=r+64)
        upk2(ohi, b0, b1);
        op[r * 128 + wl]             = a0;
        op[(r + 64) * 128 + wl]      = a1;
        op[r * 128 + wl + 64]        = b0;
        op[(r + 64) * 128 + wl + 64] = b1;
    }
}

// ---------------------------------------------------------------------------
extern "C" void kernel_launch(void* const* d_in, const int* in_sizes, int n_in,
                              void* d_out, int out_size) {
    const float* X   = (const float*)d_in[0];
    const float* w0r = (const float*)d_in[1];
    const float* w0i = (const float*)d_in[2];
    const float* w1r = (const float*)d_in[3];
    const float* w1i = (const float*)d_in[4];
    float* out = (float*)d_out;

    static bool attr_done = false;
    if (!attr_done) {
        cudaFuncSetAttribute(k_modes, cudaFuncAttributeMaxDynamicSharedMemorySize,
                             91136);
        attr_done = true;
    }

    k_transpose<<<2048, 256>>>(w0r, w0i, w1r, w1i);
    k_forward<<<1024, 128>>>(X);
    k_modes<<<512, 256, 91136>>>();
    k_inverse<<<1024, 256>>>(out);
}